// round 3
// baseline (speedup 1.0000x reference)
#include <cuda_runtime.h>

#define NN 100000
#define EE 3200000
#define IC 500
#define HC 64
#define OC 16

// ---------------- scratch (device globals; no allocation allowed) ----------------
// Feature tables natively float4-typed: OC=16 floats -> 4 float4 per node.
__device__ float4 g_h0[NN * 4];
__device__ float4 g_hA[NN * 4];
__device__ float4 g_hB[NN * 4];
__device__ float  g_dinv[NN];
__device__ int    g_deg[NN];
__device__ int    g_rowptr[NN + 1];
__device__ int    g_next[NN];
__device__ int2   g_csr[EE];   // (src, weight-as-bits), sorted by target

// ---------------- graph preprocessing ----------------
__global__ void zero_deg_kernel() {
    int i = blockIdx.x * blockDim.x + threadIdx.x;
    if (i < NN) g_deg[i] = 0;
}

__global__ void hist_kernel(const int* __restrict__ col) {
    int e = blockIdx.x * blockDim.x + threadIdx.x;
    if (e < EE) atomicAdd(&g_deg[col[e]], 1);
}

__global__ void dinv_kernel() {
    int i = blockIdx.x * blockDim.x + threadIdx.x;
    if (i < NN) g_dinv[i] = rsqrtf((float)(g_deg[i] + 1));  // +1 self-loop
}

// single-block exclusive scan of g_deg -> g_rowptr, g_next
__global__ void scan_kernel() {
    __shared__ int sums[1024];
    const int C = 98;  // 1024*98 = 100352 >= NN
    int t = threadIdx.x;
    int beg = t * C;
    int end = min(beg + C, NN);
    int s = 0;
    for (int i = beg; i < end; i++) s += g_deg[i];
    sums[t] = s;
    __syncthreads();
    for (int off = 1; off < 1024; off <<= 1) {
        int v = (t >= off) ? sums[t - off] : 0;
        __syncthreads();
        sums[t] += v;
        __syncthreads();
    }
    int run = (t == 0) ? 0 : sums[t - 1];
    for (int i = beg; i < end; i++) {
        g_rowptr[i] = run;
        g_next[i] = run;
        run += g_deg[i];
    }
    if (t == 1023) g_rowptr[NN] = sums[1023];
}

__global__ void scatter_kernel(const int* __restrict__ row,
                               const int* __restrict__ col) {
    int e = blockIdx.x * blockDim.x + threadIdx.x;
    if (e >= EE) return;
    int r = row[e];
    int c = col[e];
    float w = g_dinv[r] * g_dinv[c];
    int pos = atomicAdd(&g_next[c], 1);
    g_csr[pos] = make_int2(r, __float_as_int(w));
}

// ---------------- fused MLP: h0 = relu(x@W1 + b1) @ W2 + b2 ----------------
// 128-row tiles, 256 threads, each thread an 8x4 micro-tile of the 128x64 hidden tile.
// All vector-accessed shared storage is float4-typed (no up-casts).
__global__ __launch_bounds__(256) void mlp_kernel(const float* __restrict__ x,
                                                  const float* __restrict__ W1,
                                                  const float* __restrict__ b1,
                                                  const float* __restrict__ W2,
                                                  const float* __restrict__ b2) {
    __shared__ float4 xs4[8][33];    // [k][rowGroup]; rowGroup j = rows 4j..4j+3 (pad 33)
    __shared__ float4 ws4[8][16];    // [k][colGroup]; colGroup j = cols 4j..4j+3
    __shared__ float  hid[128][65];  // relu(h1) tile, scalar access only
    __shared__ float4 w2s4[HC * OC / 4];  // 256 float4
    __shared__ float  b1s[HC];
    __shared__ float  b2s[OC];

    int tid = threadIdx.x;
    int rowBase = blockIdx.x * 128;

    if (tid < HC) b1s[tid] = b1[tid];
    if (tid < OC) b2s[tid] = b2[tid];
    // W2 is harness-allocated (256B aligned); 1024 floats = 256 float4
    w2s4[tid] = *(const float4*)&W2[tid * 4];

    int tx = tid & 15;   // 4-col group
    int ty = tid >> 4;   // 8-row group
    float acc[8][4];
#pragma unroll
    for (int i = 0; i < 8; i++)
#pragma unroll
        for (int j = 0; j < 4; j++) acc[i][j] = 0.f;

    int lrow = tid >> 1;          // 0..127 (x stage row)
    int kq = (tid & 1) * 4;       // 0 or 4 (x stage k-quad)
    int wk = tid >> 4;            // 0..7 (W1 stage k), tid<128
    int wc = tid & 15;            // colGroup for W1 stage

    for (int kc = 0; kc < IC; kc += 8) {
        // ---- stage global -> regs ----
        float4 xv = make_float4(0.f, 0.f, 0.f, 0.f);
        int gr = rowBase + lrow;
        int gk = kc + kq;
        // x row stride = 500 floats = 2000 bytes (16B multiple); gk multiple of 4
        if (gr < NN && gk < IC) xv = *(const float4*)&x[gr * IC + gk];
        float4 wv = make_float4(0.f, 0.f, 0.f, 0.f);
        if (tid < 128) {
            int gkk = kc + wk;
            // W1 row stride = 64 floats = 256B; col offset wc*16B
            if (gkk < IC) wv = *(const float4*)&W1[gkk * HC + wc * 4];
        }

        __syncthreads();   // prior compute done before overwrite
        // scatter x (transpose): element (k, row) -> float view of xs4
        {
            float* xsf = (float*)&xs4[0][0];  // down-cast: legal
            xsf[(kq + 0) * 132 + lrow] = xv.x;
            xsf[(kq + 1) * 132 + lrow] = xv.y;
            xsf[(kq + 2) * 132 + lrow] = xv.z;
            xsf[(kq + 3) * 132 + lrow] = xv.w;
        }
        if (tid < 128) ws4[wk][wc] = wv;
        __syncthreads();

#pragma unroll
        for (int k = 0; k < 8; k++) {
            float4 a0 = xs4[k][ty * 2];
            float4 a1 = xs4[k][ty * 2 + 1];
            float4 bv = ws4[k][tx];
            float a[8] = {a0.x, a0.y, a0.z, a0.w, a1.x, a1.y, a1.z, a1.w};
            float b[4] = {bv.x, bv.y, bv.z, bv.w};
#pragma unroll
            for (int i = 0; i < 8; i++)
#pragma unroll
                for (int j = 0; j < 4; j++) acc[i][j] = fmaf(a[i], b[j], acc[i][j]);
        }
    }

    __syncthreads();
#pragma unroll
    for (int i = 0; i < 8; i++)
#pragma unroll
        for (int j = 0; j < 4; j++)
            hid[ty * 8 + i][tx * 4 + j] = fmaxf(acc[i][j] + b1s[tx * 4 + j], 0.f);
    __syncthreads();

    // GEMM2: each thread does 1 row x 8 features
    int r2 = tid >> 1;
    int fh = (tid & 1) * 8;      // 0 or 8
    float o[8];
#pragma unroll
    for (int j = 0; j < 8; j++) o[j] = b2s[fh + j];
#pragma unroll
    for (int k = 0; k < HC; k++) {
        float h = hid[r2][k];
        float4 wlo = w2s4[k * 4 + (fh >> 2)];
        float4 whi = w2s4[k * 4 + (fh >> 2) + 1];
        o[0] = fmaf(h, wlo.x, o[0]);
        o[1] = fmaf(h, wlo.y, o[1]);
        o[2] = fmaf(h, wlo.z, o[2]);
        o[3] = fmaf(h, wlo.w, o[3]);
        o[4] = fmaf(h, whi.x, o[4]);
        o[5] = fmaf(h, whi.y, o[5]);
        o[6] = fmaf(h, whi.z, o[6]);
        o[7] = fmaf(h, whi.w, o[7]);
    }
    int gr2 = rowBase + r2;
    if (gr2 < NN) {
        g_h0[gr2 * 4 + (fh >> 2)]     = make_float4(o[0], o[1], o[2], o[3]);
        g_h0[gr2 * 4 + (fh >> 2) + 1] = make_float4(o[4], o[5], o[6], o[7]);
    }
}

// ---------------- APPNP propagation step (pull, no atomics) ----------------
// warp per node; lane = (edge-slot 0..7, feature-quad 0..3)
__global__ __launch_bounds__(256) void prop_kernel(int insel, int outsel,
                                                   float4* __restrict__ dout) {
    const float4* hin = (insel == 0) ? g_h0 : ((insel == 1) ? g_hA : g_hB);
    float4* hout = (outsel == 1) ? g_hA : ((outsel == 2) ? g_hB : dout);

    int wg = (blockIdx.x * blockDim.x + threadIdx.x) >> 5;
    if (wg >= NN) return;
    int lane = threadIdx.x & 31;
    int start = g_rowptr[wg];
    int end = g_rowptr[wg + 1];
    int esub = lane >> 2;          // 0..7 edge slot
    int fq = lane & 3;             // feature quad index 0..3

    float4 acc = make_float4(0.f, 0.f, 0.f, 0.f);
    for (int e0 = start; e0 < end; e0 += 8) {
        int e = e0 + esub;
        if (e < end) {
            int2 ed = g_csr[e];                 // broadcast across 4 lanes
            float w = __int_as_float(ed.y);
            float4 h = hin[ed.x * 4 + fq];
            acc.x = fmaf(w, h.x, acc.x);
            acc.y = fmaf(w, h.y, acc.y);
            acc.z = fmaf(w, h.z, acc.z);
            acc.w = fmaf(w, h.w, acc.w);
        }
    }
    // reduce across the 8 edge slots (lane bits 2..4); feature quad preserved
#pragma unroll
    for (int off = 4; off < 32; off <<= 1) {
        acc.x += __shfl_xor_sync(0xffffffffu, acc.x, off);
        acc.y += __shfl_xor_sync(0xffffffffu, acc.y, off);
        acc.z += __shfl_xor_sync(0xffffffffu, acc.z, off);
        acc.w += __shfl_xor_sync(0xffffffffu, acc.w, off);
    }
    if (lane < 4) {
        int base = wg * 4 + lane;
        float di = g_dinv[wg];
        float sw = di * di;                      // self-loop weight
        float4 hs  = hin[base];
        float4 h0v = g_h0[base];
        float4 o;
        o.x = 0.9f * fmaf(sw, hs.x, acc.x) + 0.1f * h0v.x;
        o.y = 0.9f * fmaf(sw, hs.y, acc.y) + 0.1f * h0v.y;
        o.z = 0.9f * fmaf(sw, hs.z, acc.z) + 0.1f * h0v.z;
        o.w = 0.9f * fmaf(sw, hs.w, acc.w) + 0.1f * h0v.w;
        hout[base] = o;
    }
}

// ---------------- launch ----------------
extern "C" void kernel_launch(void* const* d_in, const int* in_sizes, int n_in,
                              void* d_out, int out_size) {
    const float* x  = (const float*)d_in[0];
    const int* ei   = (const int*)d_in[1];   // JAX default x64-disabled: int32
    const float* W1 = (const float*)d_in[2];
    const float* b1 = (const float*)d_in[3];
    const float* W2 = (const float*)d_in[4];
    const float* b2 = (const float*)d_in[5];
    float4* out = (float4*)d_out;   // harness buffer: 256B-aligned

    const int* row = ei;        // sources (edge_index[0])
    const int* col = ei + EE;   // targets (edge_index[1])

    zero_deg_kernel<<<(NN + 255) / 256, 256>>>();
    hist_kernel<<<(EE + 255) / 256, 256>>>(col);
    dinv_kernel<<<(NN + 255) / 256, 256>>>();
    scan_kernel<<<1, 1024>>>();
    scatter_kernel<<<(EE + 255) / 256, 256>>>(row, col);

    mlp_kernel<<<(NN + 127) / 128, 256>>>(x, W1, b1, W2, b2);

    int insel = 0;
    for (int k = 0; k < 10; k++) {
        int outsel = (k == 9) ? 3 : ((k & 1) ? 2 : 1);
        prop_kernel<<<(NN * 32 + 255) / 256, 256>>>(insel, outsel, out);
        insel = outsel;
    }
}

// round 4
// speedup vs baseline: 1.2527x; 1.2527x over previous
#include <cuda_runtime.h>

#define NN 100000
#define EE 3200000
#define IC 500
#define HC 64
#define OC 16
#define NB 98            // scan blocks: 98*1024 >= NN

// ---------------- scratch (device globals; no allocation allowed) ----------------
__device__ float4 g_h0[NN * 4];
__device__ float4 g_hA[NN * 4];
__device__ float4 g_hB[NN * 4];
__device__ float  g_dinv[NN];
__device__ int    g_deg[NN];
__device__ int    g_rowptr[NN + 1];
__device__ int    g_next[NN];
__device__ int2   g_csr[EE];   // (src, weight-as-bits), sorted by target
__device__ int    g_bsum[128];
__device__ int    g_boff[128];

// ---------------- graph preprocessing ----------------
__global__ void zero_deg_kernel() {
    int i = blockIdx.x * blockDim.x + threadIdx.x;
    if (i < NN) g_deg[i] = 0;
}

__global__ void hist_kernel(const int* __restrict__ col) {
    int e = blockIdx.x * blockDim.x + threadIdx.x;
    if (e < EE) atomicAdd(&g_deg[col[e]], 1);
}

__global__ void dinv_kernel() {
    int i = blockIdx.x * blockDim.x + threadIdx.x;
    if (i < NN) g_dinv[i] = rsqrtf((float)(g_deg[i] + 1));  // +1 self-loop
}

// ---- pass 1: per-block reduce of g_deg (1024 elems / block) ----
__global__ __launch_bounds__(1024) void reduce_kernel() {
    int b = blockIdx.x;
    int t = threadIdx.x;
    int i = b * 1024 + t;
    int v = (i < NN) ? g_deg[i] : 0;
#pragma unroll
    for (int off = 16; off > 0; off >>= 1) v += __shfl_down_sync(0xffffffffu, v, off);
    __shared__ int ws[32];
    int lane = t & 31, wid = t >> 5;
    if (lane == 0) ws[wid] = v;
    __syncthreads();
    if (t < 32) {
        int s = ws[t];
#pragma unroll
        for (int off = 16; off > 0; off >>= 1) s += __shfl_down_sync(0xffffffffu, s, off);
        if (t == 0) g_bsum[b] = s;
    }
}

// ---- pass 2: single tiny block scans NB partials (exclusive) ----
__global__ void scanb_kernel() {
    int t = threadIdx.x;  // 128 threads
    int v = (t < NB) ? g_bsum[t] : 0;
    int lane = t & 31, wid = t >> 5;
    int incl = v;
#pragma unroll
    for (int off = 1; off < 32; off <<= 1) {
        int n = __shfl_up_sync(0xffffffffu, incl, off);
        if (lane >= off) incl += n;
    }
    __shared__ int ws[4];
    if (lane == 31) ws[wid] = incl;
    __syncthreads();
    int base = 0;
    for (int w = 0; w < wid; w++) base += ws[w];
    int excl = base + incl - v;
    if (t < NB) g_boff[t] = excl;
    if (t == NB - 1) g_rowptr[NN] = excl + v;
}

// ---- pass 3: per-block exclusive scan + writeout ----
__global__ __launch_bounds__(1024) void writeout_kernel() {
    int b = blockIdx.x;
    int t = threadIdx.x;
    int i = b * 1024 + t;
    int v = (i < NN) ? g_deg[i] : 0;
    int lane = t & 31, wid = t >> 5;
    int incl = v;
#pragma unroll
    for (int off = 1; off < 32; off <<= 1) {
        int n = __shfl_up_sync(0xffffffffu, incl, off);
        if (lane >= off) incl += n;
    }
    __shared__ int ws[32];
    if (lane == 31) ws[wid] = incl;
    __syncthreads();
    if (t < 32) {
        int s = ws[t];
#pragma unroll
        for (int off = 1; off < 32; off <<= 1) {
            int n = __shfl_up_sync(0xffffffffu, s, off);
            if (lane >= off) s += n;
        }
        ws[t] = s;
    }
    __syncthreads();
    int warpbase = (wid > 0) ? ws[wid - 1] : 0;
    int excl = g_boff[b] + warpbase + incl - v;
    if (i < NN) {
        g_rowptr[i] = excl;
        g_next[i] = excl;
    }
}

__global__ void scatter_kernel(const int* __restrict__ row,
                               const int* __restrict__ col) {
    int e = blockIdx.x * blockDim.x + threadIdx.x;
    if (e >= EE) return;
    int r = row[e];
    int c = col[e];
    float w = g_dinv[r] * g_dinv[c];
    int pos = atomicAdd(&g_next[c], 1);
    g_csr[pos] = make_int2(r, __float_as_int(w));
}

// ---------------- fused MLP: h0 = relu(x@W1 + b1) @ W2 + b2 ----------------
__global__ __launch_bounds__(256) void mlp_kernel(const float* __restrict__ x,
                                                  const float* __restrict__ W1,
                                                  const float* __restrict__ b1,
                                                  const float* __restrict__ W2,
                                                  const float* __restrict__ b2) {
    __shared__ float4 xs4[8][33];    // [k][rowGroup]; rowGroup j = rows 4j..4j+3 (pad 33)
    __shared__ float4 ws4[8][16];    // [k][colGroup]
    __shared__ float  hid[128][65];  // relu(h1) tile, scalar access only
    __shared__ float4 w2s4[HC * OC / 4];
    __shared__ float  b1s[HC];
    __shared__ float  b2s[OC];

    int tid = threadIdx.x;
    int rowBase = blockIdx.x * 128;

    if (tid < HC) b1s[tid] = b1[tid];
    if (tid < OC) b2s[tid] = b2[tid];
    w2s4[tid] = *(const float4*)&W2[tid * 4];

    int tx = tid & 15;
    int ty = tid >> 4;
    float acc[8][4];
#pragma unroll
    for (int i = 0; i < 8; i++)
#pragma unroll
        for (int j = 0; j < 4; j++) acc[i][j] = 0.f;

    int lrow = tid >> 1;
    int kq = (tid & 1) * 4;
    int wk = tid >> 4;
    int wc = tid & 15;

    for (int kc = 0; kc < IC; kc += 8) {
        float4 xv = make_float4(0.f, 0.f, 0.f, 0.f);
        int gr = rowBase + lrow;
        int gk = kc + kq;
        if (gr < NN && gk < IC) xv = *(const float4*)&x[gr * IC + gk];
        float4 wv = make_float4(0.f, 0.f, 0.f, 0.f);
        if (tid < 128) {
            int gkk = kc + wk;
            if (gkk < IC) wv = *(const float4*)&W1[gkk * HC + wc * 4];
        }

        __syncthreads();
        {
            float* xsf = (float*)&xs4[0][0];
            xsf[(kq + 0) * 132 + lrow] = xv.x;
            xsf[(kq + 1) * 132 + lrow] = xv.y;
            xsf[(kq + 2) * 132 + lrow] = xv.z;
            xsf[(kq + 3) * 132 + lrow] = xv.w;
        }
        if (tid < 128) ws4[wk][wc] = wv;
        __syncthreads();

#pragma unroll
        for (int k = 0; k < 8; k++) {
            float4 a0 = xs4[k][ty * 2];
            float4 a1 = xs4[k][ty * 2 + 1];
            float4 bv = ws4[k][tx];
            float a[8] = {a0.x, a0.y, a0.z, a0.w, a1.x, a1.y, a1.z, a1.w};
            float b[4] = {bv.x, bv.y, bv.z, bv.w};
#pragma unroll
            for (int i = 0; i < 8; i++)
#pragma unroll
                for (int j = 0; j < 4; j++) acc[i][j] = fmaf(a[i], b[j], acc[i][j]);
        }
    }

    __syncthreads();
#pragma unroll
    for (int i = 0; i < 8; i++)
#pragma unroll
        for (int j = 0; j < 4; j++)
            hid[ty * 8 + i][tx * 4 + j] = fmaxf(acc[i][j] + b1s[tx * 4 + j], 0.f);
    __syncthreads();

    int r2 = tid >> 1;
    int fh = (tid & 1) * 8;
    float o[8];
#pragma unroll
    for (int j = 0; j < 8; j++) o[j] = b2s[fh + j];
#pragma unroll
    for (int k = 0; k < HC; k++) {
        float h = hid[r2][k];
        float4 wlo = w2s4[k * 4 + (fh >> 2)];
        float4 whi = w2s4[k * 4 + (fh >> 2) + 1];
        o[0] = fmaf(h, wlo.x, o[0]);
        o[1] = fmaf(h, wlo.y, o[1]);
        o[2] = fmaf(h, wlo.z, o[2]);
        o[3] = fmaf(h, wlo.w, o[3]);
        o[4] = fmaf(h, whi.x, o[4]);
        o[5] = fmaf(h, whi.y, o[5]);
        o[6] = fmaf(h, whi.z, o[6]);
        o[7] = fmaf(h, whi.w, o[7]);
    }
    int gr2 = rowBase + r2;
    if (gr2 < NN) {
        g_h0[gr2 * 4 + (fh >> 2)]     = make_float4(o[0], o[1], o[2], o[3]);
        g_h0[gr2 * 4 + (fh >> 2) + 1] = make_float4(o[4], o[5], o[6], o[7]);
    }
}

// ---------------- APPNP propagation step (pull, no atomics) ----------------
__global__ __launch_bounds__(256) void prop_kernel(int insel, int outsel,
                                                   float4* __restrict__ dout) {
    const float4* hin = (insel == 0) ? g_h0 : ((insel == 1) ? g_hA : g_hB);
    float4* hout = (outsel == 1) ? g_hA : ((outsel == 2) ? g_hB : dout);

    int wg = (blockIdx.x * blockDim.x + threadIdx.x) >> 5;
    if (wg >= NN) return;
    int lane = threadIdx.x & 31;
    int start = g_rowptr[wg];
    int end = g_rowptr[wg + 1];
    int esub = lane >> 2;
    int fq = lane & 3;

    float4 acc = make_float4(0.f, 0.f, 0.f, 0.f);
    for (int e0 = start; e0 < end; e0 += 8) {
        int e = e0 + esub;
        if (e < end) {
            int2 ed = g_csr[e];
            float w = __int_as_float(ed.y);
            float4 h = hin[ed.x * 4 + fq];
            acc.x = fmaf(w, h.x, acc.x);
            acc.y = fmaf(w, h.y, acc.y);
            acc.z = fmaf(w, h.z, acc.z);
            acc.w = fmaf(w, h.w, acc.w);
        }
    }
#pragma unroll
    for (int off = 4; off < 32; off <<= 1) {
        acc.x += __shfl_xor_sync(0xffffffffu, acc.x, off);
        acc.y += __shfl_xor_sync(0xffffffffu, acc.y, off);
        acc.z += __shfl_xor_sync(0xffffffffu, acc.z, off);
        acc.w += __shfl_xor_sync(0xffffffffu, acc.w, off);
    }
    if (lane < 4) {
        int base = wg * 4 + lane;
        float di = g_dinv[wg];
        float sw = di * di;
        float4 hs  = hin[base];
        float4 h0v = g_h0[base];
        float4 o;
        o.x = 0.9f * fmaf(sw, hs.x, acc.x) + 0.1f * h0v.x;
        o.y = 0.9f * fmaf(sw, hs.y, acc.y) + 0.1f * h0v.y;
        o.z = 0.9f * fmaf(sw, hs.z, acc.z) + 0.1f * h0v.z;
        o.w = 0.9f * fmaf(sw, hs.w, acc.w) + 0.1f * h0v.w;
        hout[base] = o;
    }
}

// ---------------- launch ----------------
extern "C" void kernel_launch(void* const* d_in, const int* in_sizes, int n_in,
                              void* d_out, int out_size) {
    const float* x  = (const float*)d_in[0];
    const int* ei   = (const int*)d_in[1];   // int32 (JAX x64-disabled)
    const float* W1 = (const float*)d_in[2];
    const float* b1 = (const float*)d_in[3];
    const float* W2 = (const float*)d_in[4];
    const float* b2 = (const float*)d_in[5];
    float4* out = (float4*)d_out;

    const int* row = ei;        // sources
    const int* col = ei + EE;   // targets

    zero_deg_kernel<<<(NN + 255) / 256, 256>>>();
    hist_kernel<<<(EE + 255) / 256, 256>>>(col);
    dinv_kernel<<<(NN + 255) / 256, 256>>>();
    reduce_kernel<<<NB, 1024>>>();
    scanb_kernel<<<1, 128>>>();
    writeout_kernel<<<NB, 1024>>>();
    scatter_kernel<<<(EE + 255) / 256, 256>>>(row, col);

    mlp_kernel<<<(NN + 127) / 128, 256>>>(x, W1, b1, W2, b2);

    int insel = 0;
    for (int k = 0; k < 10; k++) {
        int outsel = (k == 9) ? 3 : ((k & 1) ? 2 : 1);
        prop_kernel<<<(NN * 32 + 255) / 256, 256>>>(insel, outsel, out);
        insel = outsel;
    }
}

// round 6
// speedup vs baseline: 1.7844x; 1.4245x over previous
#include <cuda_runtime.h>
#include <cuda_bf16.h>
#include <cstdint>

#define NN 100000
#define EE 3200000
#define IC 500
#define HC 64
#define OC 16
#define NB 98            // scan blocks: 98*1024 >= NN

// ---------------- scratch (device globals; no allocation allowed) ----------------
__device__ float4 g_h0[NN * 4];   // y0 = dinv .* h0
__device__ float4 g_hA[NN * 4];
__device__ float4 g_hB[NN * 4];
__device__ float  g_dinv[NN];
__device__ int    g_deg[NN];
__device__ int    g_rowptr[NN + 1];
__device__ int    g_next[NN];
__device__ int    g_src[EE];      // CSR: source index only (y-space, no weights)
__device__ int    g_bsum[128];
__device__ int    g_boff[128];

// ---------------- graph preprocessing ----------------
__global__ void zero_deg_kernel() {
    int i = blockIdx.x * blockDim.x + threadIdx.x;
    if (i < NN) g_deg[i] = 0;
}

__global__ void hist_kernel(const int* __restrict__ col) {
    int e = blockIdx.x * blockDim.x + threadIdx.x;
    if (e < EE) atomicAdd(&g_deg[col[e]], 1);
}

__global__ void dinv_kernel() {
    int i = blockIdx.x * blockDim.x + threadIdx.x;
    if (i < NN) g_dinv[i] = rsqrtf((float)(g_deg[i] + 1));  // +1 self-loop
}

__global__ __launch_bounds__(1024) void reduce_kernel() {
    int b = blockIdx.x;
    int t = threadIdx.x;
    int i = b * 1024 + t;
    int v = (i < NN) ? g_deg[i] : 0;
#pragma unroll
    for (int off = 16; off > 0; off >>= 1) v += __shfl_down_sync(0xffffffffu, v, off);
    __shared__ int ws[32];
    int lane = t & 31, wid = t >> 5;
    if (lane == 0) ws[wid] = v;
    __syncthreads();
    if (t < 32) {
        int s = ws[t];
#pragma unroll
        for (int off = 16; off > 0; off >>= 1) s += __shfl_down_sync(0xffffffffu, s, off);
        if (t == 0) g_bsum[b] = s;
    }
}

__global__ void scanb_kernel() {
    int t = threadIdx.x;  // 128 threads
    int v = (t < NB) ? g_bsum[t] : 0;
    int lane = t & 31, wid = t >> 5;
    int incl = v;
#pragma unroll
    for (int off = 1; off < 32; off <<= 1) {
        int n = __shfl_up_sync(0xffffffffu, incl, off);
        if (lane >= off) incl += n;
    }
    __shared__ int ws[4];
    if (lane == 31) ws[wid] = incl;
    __syncthreads();
    int base = 0;
    for (int w = 0; w < wid; w++) base += ws[w];
    int excl = base + incl - v;
    if (t < NB) g_boff[t] = excl;
    if (t == NB - 1) g_rowptr[NN] = excl + v;
}

__global__ __launch_bounds__(1024) void writeout_kernel() {
    int b = blockIdx.x;
    int t = threadIdx.x;
    int i = b * 1024 + t;
    int v = (i < NN) ? g_deg[i] : 0;
    int lane = t & 31, wid = t >> 5;
    int incl = v;
#pragma unroll
    for (int off = 1; off < 32; off <<= 1) {
        int n = __shfl_up_sync(0xffffffffu, incl, off);
        if (lane >= off) incl += n;
    }
    __shared__ int ws[32];
    if (lane == 31) ws[wid] = incl;
    __syncthreads();
    if (t < 32) {
        int s = ws[t];
#pragma unroll
        for (int off = 1; off < 32; off <<= 1) {
            int n = __shfl_up_sync(0xffffffffu, s, off);
            if (lane >= off) s += n;
        }
        ws[t] = s;
    }
    __syncthreads();
    int warpbase = (wid > 0) ? ws[wid - 1] : 0;
    int excl = g_boff[b] + warpbase + incl - v;
    if (i < NN) {
        g_rowptr[i] = excl;
        g_next[i] = excl;
    }
}

__global__ void scatter_kernel(const int* __restrict__ row,
                               const int* __restrict__ col) {
    int e = blockIdx.x * blockDim.x + threadIdx.x;
    if (e >= EE) return;
    int c = col[e];
    int pos = atomicAdd(&g_next[c], 1);
    g_src[pos] = row[e];
}

// =====================================================================
// MLP: y0 = dinv .* ( relu(x@W1 + b1) @ W2 + b2 )
// via mma.sync m16n8k16 bf16, split-precision (Ah*Bh + Ah*Bl + Al*Bh)
// Smem staged in FRAGMENT layout: A frag = uint4 (1 LDS.128/warp),
// B frag = uint2 (1 LDS.64/warp).
// =====================================================================
#define KCH 64
// smem byte offsets (dynamic smem)
#define AF_HI 0u          // 8 stripes * 4 ksteps * 32 lanes * 16B = 16384
#define AF_LO 16384u
#define BF_HI 32768u      // 8 ntiles * 4 ksteps * 32 lanes * 8B = 8192
#define BF_LO 40960u
#define W2_OFF 49152u     // 1024 f32 = 4096
#define B1_OFF 53248u     // 256
#define B2_OFF 53504u     // 64
#define SMEM_TOT 53568
// hidden tile (128 x 65 f32 = 33280B) overlaps frag region at offset 0
#define HID_STRIDE 65

__device__ __forceinline__ void split_pack(float a, float b, uint32_t& hi, uint32_t& lo) {
    __nv_bfloat16 ah = __float2bfloat16(a);
    __nv_bfloat16 bh = __float2bfloat16(b);
    __nv_bfloat16 al = __float2bfloat16(a - __bfloat162float(ah));
    __nv_bfloat16 bl = __float2bfloat16(b - __bfloat162float(bh));
    hi = ((uint32_t)__bfloat16_as_ushort(bh) << 16) | __bfloat16_as_ushort(ah);
    lo = ((uint32_t)__bfloat16_as_ushort(bl) << 16) | __bfloat16_as_ushort(al);
}

__device__ __forceinline__ void mma16816(float* c, const uint32_t* a, uint32_t b0, uint32_t b1) {
    asm volatile(
        "mma.sync.aligned.m16n8k16.row.col.f32.bf16.bf16.f32 "
        "{%0,%1,%2,%3}, {%4,%5,%6,%7}, {%8,%9}, {%0,%1,%2,%3};"
        : "+f"(c[0]), "+f"(c[1]), "+f"(c[2]), "+f"(c[3])
        : "r"(a[0]), "r"(a[1]), "r"(a[2]), "r"(a[3]), "r"(b0), "r"(b1));
}

__global__ __launch_bounds__(256, 2)
void mlp_mma_kernel(const float* __restrict__ x,
                    const float* __restrict__ W1,
                    const float* __restrict__ b1,
                    const float* __restrict__ W2,
                    const float* __restrict__ b2) {
    extern __shared__ char smem[];
    int tid = threadIdx.x;
    int wid = tid >> 5;
    int lane = tid & 31;
    int rowBase = blockIdx.x * 128;

    // constants into smem
    *(float4*)(smem + W2_OFF + tid * 16) = *(const float4*)&W2[tid * 4];
    if (tid < HC) *(float*)(smem + B1_OFF + tid * 4) = b1[tid];
    if (tid < OC) *(float*)(smem + B2_OFF + tid * 4) = b2[tid];

    uint32_t* afh = (uint32_t*)(smem + AF_HI);
    uint32_t* afl = (uint32_t*)(smem + AF_LO);
    uint32_t* bfh = (uint32_t*)(smem + BF_HI);
    uint32_t* bfl = (uint32_t*)(smem + BF_LO);

    float acc[8][4];
#pragma unroll
    for (int nt = 0; nt < 8; nt++)
#pragma unroll
        for (int j = 0; j < 4; j++) acc[nt][j] = 0.f;

    for (int c = 0; c < 8; c++) {
        int kc = c * KCH;
        __syncthreads();   // previous chunk's consumers done

        // ---- stage A: x[rowBase..+128][kc..+64] -> bf16 hi/lo frags ----
        // 2048 float4 per chunk; 256 threads x 8
#pragma unroll
        for (int i = 0; i < 8; i++) {
            int idx = i * 256 + tid;
            int row = idx >> 4;           // 0..127
            int kq = (idx & 15) * 4;      // 0..60, step 4
            int grow = rowBase + row;
            int gk = kc + kq;
            float4 xv = make_float4(0.f, 0.f, 0.f, 0.f);
            if (grow < NN && gk < IC) xv = *(const float4*)&x[grow * IC + gk];
            uint32_t h0, l0, h1, l1;
            split_pack(xv.x, xv.y, h0, l0);   // pair (kq, kq+1)
            split_pack(xv.z, xv.w, h1, l1);   // pair (kq+2, kq+3)
            int w = row >> 4;
            // pair 0
            {
                int kl = kq;
                int s = kl >> 4;
                int ln = ((row & 7) << 2) | ((kl >> 1) & 3);
                int comp = ((kl & 15) >= 8 ? 2 : 0) + ((row & 15) >= 8 ? 1 : 0);
                int off = ((w * 4 + s) * 32 + ln) * 4 + comp;
                afh[off] = h0;
                afl[off] = l0;
            }
            // pair 1
            {
                int kl = kq + 2;
                int s = kl >> 4;
                int ln = ((row & 7) << 2) | ((kl >> 1) & 3);
                int comp = ((kl & 15) >= 8 ? 2 : 0) + ((row & 15) >= 8 ? 1 : 0);
                int off = ((w * 4 + s) * 32 + ln) * 4 + comp;
                afh[off] = h1;
                afl[off] = l1;
            }
        }
        // ---- stage B: W1^T  pairs along k ----
        {
            int n = tid & 63;
            int kb = (tid >> 6) * 16;     // 16 k values = 8 pairs per thread
            int nt = n >> 3;
            int lnbase = (n & 7) << 2;
#pragma unroll
            for (int i = 0; i < 8; i++) {
                int kl = kb + 2 * i;
                int gk0 = kc + kl;
                float w0 = (gk0 < IC) ? W1[gk0 * HC + n] : 0.f;
                float w1 = (gk0 + 1 < IC) ? W1[(gk0 + 1) * HC + n] : 0.f;
                uint32_t h, l;
                split_pack(w0, w1, h, l);
                int s = kl >> 4;
                int ln = lnbase | ((kl >> 1) & 3);
                int comp = (kl & 15) >= 8 ? 1 : 0;
                int off = ((nt * 4 + s) * 32 + ln) * 2 + comp;
                bfh[off] = h;
                bfl[off] = l;
            }
        }
        __syncthreads();

        // ---- compute: warp = 16-row stripe; 4 ksteps x 8 ntiles x 3 mma ----
        const uint4* afh4 = (const uint4*)(smem + AF_HI);
        const uint4* afl4 = (const uint4*)(smem + AF_LO);
        const uint2* bfh2 = (const uint2*)(smem + BF_HI);
        const uint2* bfl2 = (const uint2*)(smem + BF_LO);
#pragma unroll
        for (int s = 0; s < 4; s++) {
            uint4 ah4 = afh4[(wid * 4 + s) * 32 + lane];
            uint4 al4 = afl4[(wid * 4 + s) * 32 + lane];
            uint32_t ah[4] = {ah4.x, ah4.y, ah4.z, ah4.w};
            uint32_t al[4] = {al4.x, al4.y, al4.z, al4.w};
#pragma unroll
            for (int nt = 0; nt < 8; nt++) {
                uint2 bh = bfh2[(nt * 4 + s) * 32 + lane];
                uint2 bl = bfl2[(nt * 4 + s) * 32 + lane];
                mma16816(acc[nt], ah, bh.x, bh.y);
                mma16816(acc[nt], ah, bl.x, bl.y);
                mma16816(acc[nt], al, bh.x, bh.y);
            }
        }
    }

    // ---- hidden tile -> smem (bias + relu applied) ----
    __syncthreads();   // frag region free for reuse
    {
        float* hid = (float*)smem;
        const float* b1s = (const float*)(smem + B1_OFF);
        int r0 = wid * 16 + (lane >> 2);
        int c0 = (lane & 3) * 2;
#pragma unroll
        for (int nt = 0; nt < 8; nt++) {
            int col = nt * 8 + c0;
            float bcol0 = b1s[col];
            float bcol1 = b1s[col + 1];
            hid[r0 * HID_STRIDE + col]           = fmaxf(acc[nt][0] + bcol0, 0.f);
            hid[r0 * HID_STRIDE + col + 1]       = fmaxf(acc[nt][1] + bcol1, 0.f);
            hid[(r0 + 8) * HID_STRIDE + col]     = fmaxf(acc[nt][2] + bcol0, 0.f);
            hid[(r0 + 8) * HID_STRIDE + col + 1] = fmaxf(acc[nt][3] + bcol1, 0.f);
        }
    }
    __syncthreads();

    // ---- GEMM2 epilogue: thread = one row (tid < 128) ----
    if (tid < 128) {
        const float* hid = (const float*)smem;
        const float* b2s = (const float*)(smem + B2_OFF);
        const float4* w2s = (const float4*)(smem + W2_OFF);
        const float* hrow = &hid[tid * HID_STRIDE];

        float4 o0 = make_float4(b2s[0], b2s[1], b2s[2], b2s[3]);
        float4 o1 = make_float4(b2s[4], b2s[5], b2s[6], b2s[7]);
        float4 o2 = make_float4(b2s[8], b2s[9], b2s[10], b2s[11]);
        float4 o3 = make_float4(b2s[12], b2s[13], b2s[14], b2s[15]);
#pragma unroll
        for (int k = 0; k < HC; k++) {
            float h = hrow[k];
            float4 wa = w2s[k * 4 + 0];
            float4 wb = w2s[k * 4 + 1];
            float4 wc = w2s[k * 4 + 2];
            float4 wd = w2s[k * 4 + 3];
            o0.x = fmaf(h, wa.x, o0.x); o0.y = fmaf(h, wa.y, o0.y);
            o0.z = fmaf(h, wa.z, o0.z); o0.w = fmaf(h, wa.w, o0.w);
            o1.x = fmaf(h, wb.x, o1.x); o1.y = fmaf(h, wb.y, o1.y);
            o1.z = fmaf(h, wb.z, o1.z); o1.w = fmaf(h, wb.w, o1.w);
            o2.x = fmaf(h, wc.x, o2.x); o2.y = fmaf(h, wc.y, o2.y);
            o2.z = fmaf(h, wc.z, o2.z); o2.w = fmaf(h, wc.w, o2.w);
            o3.x = fmaf(h, wd.x, o3.x); o3.y = fmaf(h, wd.y, o3.y);
            o3.z = fmaf(h, wd.z, o3.z); o3.w = fmaf(h, wd.w, o3.w);
        }
        int grow = rowBase + tid;
        if (grow < NN) {
            float di = g_dinv[grow];   // y0 = dinv * h0
            o0.x *= di; o0.y *= di; o0.z *= di; o0.w *= di;
            o1.x *= di; o1.y *= di; o1.z *= di; o1.w *= di;
            o2.x *= di; o2.y *= di; o2.z *= di; o2.w *= di;
            o3.x *= di; o3.y *= di; o3.z *= di; o3.w *= di;
            g_h0[grow * 4 + 0] = o0;
            g_h0[grow * 4 + 1] = o1;
            g_h0[grow * 4 + 2] = o2;
            g_h0[grow * 4 + 3] = o3;
        }
    }
}

// ---------------- APPNP propagation in y-space (pull, no atomics) ----------------
// y_{k+1}[c] = 0.9*dinv[c]^2*(sum_in y_k + y_k[c]) + 0.1*y0[c]
// final:  out[c] = 0.9*dinv[c]*(sum_in y_k + y_k[c]) + 0.1*y0[c]/dinv[c]
__global__ __launch_bounds__(256) void prop_kernel(int insel, int outsel,
                                                   float4* __restrict__ dout) {
    const float4* hin = (insel == 0) ? g_h0 : ((insel == 1) ? g_hA : g_hB);
    float4* hout = (outsel == 1) ? g_hA : ((outsel == 2) ? g_hB : dout);
    bool final_step = (outsel == 3);

    int wg = (blockIdx.x * blockDim.x + threadIdx.x) >> 5;
    if (wg >= NN) return;
    int lane = threadIdx.x & 31;
    int start = g_rowptr[wg];
    int end = g_rowptr[wg + 1];
    int esub = lane >> 2;
    int fq = lane & 3;

    float4 acc = make_float4(0.f, 0.f, 0.f, 0.f);
    for (int e0 = start; e0 < end; e0 += 8) {
        int e = e0 + esub;
        if (e < end) {
            int src = g_src[e];
            float4 h = hin[src * 4 + fq];
            acc.x += h.x;
            acc.y += h.y;
            acc.z += h.z;
            acc.w += h.w;
        }
    }
#pragma unroll
    for (int off = 4; off < 32; off <<= 1) {
        acc.x += __shfl_xor_sync(0xffffffffu, acc.x, off);
        acc.y += __shfl_xor_sync(0xffffffffu, acc.y, off);
        acc.z += __shfl_xor_sync(0xffffffffu, acc.z, off);
        acc.w += __shfl_xor_sync(0xffffffffu, acc.w, off);
    }
    if (lane < 4) {
        int base = wg * 4 + lane;
        float di = g_dinv[wg];
        float4 ys = hin[base];
        float4 y0 = g_h0[base];
        acc.x += ys.x; acc.y += ys.y; acc.z += ys.z; acc.w += ys.w;
        float4 o;
        if (!final_step) {
            float d2 = di * di;
            o.x = 0.9f * d2 * acc.x + 0.1f * y0.x;
            o.y = 0.9f * d2 * acc.y + 0.1f * y0.y;
            o.z = 0.9f * d2 * acc.z + 0.1f * y0.z;
            o.w = 0.9f * d2 * acc.w + 0.1f * y0.w;
        } else {
            float inv = 1.0f / di;
            o.x = 0.9f * di * acc.x + 0.1f * y0.x * inv;
            o.y = 0.9f * di * acc.y + 0.1f * y0.y * inv;
            o.z = 0.9f * di * acc.z + 0.1f * y0.z * inv;
            o.w = 0.9f * di * acc.w + 0.1f * y0.w * inv;
        }
        hout[base] = o;
    }
}

// ---------------- launch ----------------
extern "C" void kernel_launch(void* const* d_in, const int* in_sizes, int n_in,
                              void* d_out, int out_size) {
    const float* x  = (const float*)d_in[0];
    const int* ei   = (const int*)d_in[1];   // int32 (JAX x64-disabled)
    const float* W1 = (const float*)d_in[2];
    const float* b1 = (const float*)d_in[3];
    const float* W2 = (const float*)d_in[4];
    const float* b2 = (const float*)d_in[5];
    float4* out = (float4*)d_out;

    const int* row = ei;        // sources
    const int* col = ei + EE;   // targets

    zero_deg_kernel<<<(NN + 255) / 256, 256>>>();
    hist_kernel<<<(EE + 255) / 256, 256>>>(col);
    dinv_kernel<<<(NN + 255) / 256, 256>>>();
    reduce_kernel<<<NB, 1024>>>();
    scanb_kernel<<<1, 128>>>();
    writeout_kernel<<<NB, 1024>>>();
    scatter_kernel<<<(EE + 255) / 256, 256>>>(row, col);

    cudaFuncSetAttribute(mlp_mma_kernel, cudaFuncAttributeMaxDynamicSharedMemorySize, SMEM_TOT);
    mlp_mma_kernel<<<(NN + 127) / 128, 256, SMEM_TOT>>>(x, W1, b1, W2, b2);

    int insel = 0;
    for (int k = 0; k < 10; k++) {
        int outsel = (k == 9) ? 3 : ((k & 1) ? 2 : 1);
        prop_kernel<<<(NN * 32 + 255) / 256, 256>>>(insel, outsel, out);
        insel = outsel;
    }
}